// round 10
// baseline (speedup 1.0000x reference)
#include <cuda_runtime.h>

#define S 32
#define CCH 3
#define NSTEPS 4
#define DT_C 0.15f
#define EPS_C 1e-6f
#define NTHREADS 512

// Precomputed Thomas factors, de-interleaved: p = 1/denom, q = a/denom
// (== cstar since a==c). Packed per line as float[32].
__device__ float g_px[NSTEPS * CCH * S * S];
__device__ float g_qx[NSTEPS * CCH * S * S];
__device__ float g_py[NSTEPS * CCH * S * S];
__device__ float g_qy[NSTEPS * CCH * S * S];

__global__ void precompute_kernel(const float* __restrict__ alpha_base,
                                  const float* __restrict__ beta_base,
                                  const float* __restrict__ alpha_tc,
                                  const float* __restrict__ beta_tc) {
    int idx = blockIdx.x * blockDim.x + threadIdx.x;
    const int NLINES = NSTEPS * CCH * S;      // 384 per direction
    if (idx >= 2 * NLINES) return;
    int dir  = idx / NLINES;                  // 0 = x (solve along W), 1 = y (along H)
    int r    = idx % NLINES;
    int t    = r / (CCH * S);
    int c    = (r / S) % CCH;
    int line = r % S;                          // h for x-dir, w for y-dir

    float tv = (float)t * DT_C;
    const float* base = dir ? beta_base : alpha_base;
    const float* tc   = dir ? beta_tc   : alpha_tc;

    float raw[S];
    #pragma unroll
    for (int i = 0; i < S; i++) {
        int h = dir ? i : line;
        int w = dir ? line : i;
        int off = (c * S + h) * S + w;
        raw[i] = fmaxf(base[off] + tc[off] * tv, EPS_C);
    }
    float dt = dir ? DT_C : (DT_C * 0.5f);
    float cf[S];
    #pragma unroll
    for (int i = 0; i < S; i++) {
        float lm = raw[i == 0 ? 0 : i - 1];
        float rm = raw[i == S - 1 ? S - 1 : i + 1];
        cf[i] = (lm + raw[i] + rm) * (1.0f / 3.0f) * dt;
    }
    float* outp = dir ? g_py : g_px;
    float* outq = dir ? g_qy : g_qx;
    long ob = ((long)(t * CCH + c) * S + line) * S;
    float cp = 0.0f;
    #pragma unroll
    for (int i = 0; i < S; i++) {
        float b = 1.0f + 2.0f * cf[i];
        if (i == 0 || i == S - 1) b = 1.0f + cf[i];
        float a = -cf[i];
        float denom = b - a * cp + EPS_C;     // matches reference (+EPS every step)
        float p = 1.0f / denom;
        float q = a * p;                      // also equals cstar_i (a == c)
        cp = q;
        outp[ob + i] = p;
        outq[ob + i] = q;
    }
}

// Dual tridiagonal sweep: one warp solves TWO lines (A, B) with the chains
// interleaved so every latency window has an independent stream to issue.
// Coefficients via broadcast LDS.128 (asm volatile pins them -> no hoist,
// no spills). Each line's p/q tables: 32 floats, 128B apart (A then B).
template<bool COL, bool IN_SMEM, bool OUT_SMEM>
__device__ __forceinline__ void solve_pair(float* __restrict__ tile,
                                           float (&rA)[S], float (&rB)[S],
                                           unsigned pA, unsigned qA,
                                           int lineA, int lane, float scale) {
    const unsigned pB = pA + 128u, qB = qA + 128u;
    const int lineB = lineA + 1;
    float prevA = 0.0f, prevB = 0.0f;
    #pragma unroll
    for (int j = 0; j < 8; j++) {
        float pa0, pa1, pa2, pa3, qa0, qa1, qa2, qa3;
        float pb0, pb1, pb2, pb3, qb0, qb1, qb2, qb3;
        asm volatile("ld.shared.v4.f32 {%0,%1,%2,%3},[%4];"
                     : "=f"(pa0), "=f"(pa1), "=f"(pa2), "=f"(pa3) : "r"(pA + 16u * j));
        asm volatile("ld.shared.v4.f32 {%0,%1,%2,%3},[%4];"
                     : "=f"(qa0), "=f"(qa1), "=f"(qa2), "=f"(qa3) : "r"(qA + 16u * j));
        asm volatile("ld.shared.v4.f32 {%0,%1,%2,%3},[%4];"
                     : "=f"(pb0), "=f"(pb1), "=f"(pb2), "=f"(pb3) : "r"(pB + 16u * j));
        asm volatile("ld.shared.v4.f32 {%0,%1,%2,%3},[%4];"
                     : "=f"(qb0), "=f"(qb1), "=f"(qb2), "=f"(qb3) : "r"(qB + 16u * j));
        #pragma unroll
        for (int e = 0; e < 4; e++) {
            int i = 4 * j + e;
            float pa = e == 0 ? pa0 : e == 1 ? pa1 : e == 2 ? pa2 : pa3;
            float qa = e == 0 ? qa0 : e == 1 ? qa1 : e == 2 ? qa2 : qa3;
            float pb = e == 0 ? pb0 : e == 1 ? pb1 : e == 2 ? pb2 : pb3;
            float qb = e == 0 ? qb0 : e == 1 ? qb1 : e == 2 ? qb2 : qb3;
            float dA, dB;
            if (IN_SMEM) {
                int eA = COL ? (i * S + lineA) : (lineA * S + i);
                int eB = COL ? (i * S + lineB) : (lineB * S + i);
                dA = tile[eA * 33 + lane];
                dB = tile[eB * 33 + lane];
            } else { dA = rA[i]; dB = rB[i]; }
            prevA = fmaf(-qa, prevA, dA * pa);    // (d - a*prev)/denom
            prevB = fmaf(-qb, prevB, dB * pb);
            rA[i] = prevA;
            rB[i] = prevB;
        }
    }
    float xA = rA[S - 1], xB = rB[S - 1];          // cstar[N-1] irrelevant
    rA[S - 1] = xA * scale;
    rB[S - 1] = xB * scale;
    if (OUT_SMEM) {
        int eA = COL ? ((S - 1) * S + lineA) : (lineA * S + (S - 1));
        int eB = COL ? ((S - 1) * S + lineB) : (lineB * S + (S - 1));
        tile[eA * 33 + lane] = xA * scale;
        tile[eB * 33 + lane] = xB * scale;
    }
    #pragma unroll
    for (int j = 7; j >= 0; j--) {
        float qa0, qa1, qa2, qa3, qb0, qb1, qb2, qb3;   // q-only reload
        asm volatile("ld.shared.v4.f32 {%0,%1,%2,%3},[%4];"
                     : "=f"(qa0), "=f"(qa1), "=f"(qa2), "=f"(qa3) : "r"(qA + 16u * j));
        asm volatile("ld.shared.v4.f32 {%0,%1,%2,%3},[%4];"
                     : "=f"(qb0), "=f"(qb1), "=f"(qb2), "=f"(qb3) : "r"(qB + 16u * j));
        #pragma unroll
        for (int e = 3; e >= 0; e--) {
            int i = 4 * j + e;
            if (i == S - 1) continue;              // seed already placed
            float qa = e == 0 ? qa0 : e == 1 ? qa1 : e == 2 ? qa2 : qa3;
            float qb = e == 0 ? qb0 : e == 1 ? qb1 : e == 2 ? qb2 : qb3;
            xA = fmaf(-qa, xA, rA[i]);             // cstar_i == q_i
            xB = fmaf(-qb, xB, rB[i]);
            rA[i] = xA * scale;
            rB[i] = xB * scale;
            if (OUT_SMEM) {
                int eA = COL ? (i * S + lineA) : (lineA * S + i);
                int eB = COL ? (i * S + lineB) : (lineB * S + i);
                tile[eA * 33 + lane] = xA * scale;
                tile[eB * 33 + lane] = xB * scale;
            }
        }
    }
}

// Dynamic smem: [ spx | sqx | spy | sqy : 4096 floats each | tile: 33792 f ]
#define COEF_F_PER_TBL (NSTEPS * S * S)           // 4096 floats = 16KB per table
#define SMEM_BYTES (4 * COEF_F_PER_TBL * 4 + S * S * 33 * 4)   // 200704 B

__global__ void __launch_bounds__(NTHREADS, 1)
adi_kernel(const float* __restrict__ U, const float* __restrict__ coupling,
           float* __restrict__ Out) {
    extern __shared__ float smem[];
    float* spx  = smem;
    float* sqx  = spx + COEF_F_PER_TBL;
    float* spy  = sqx + COEF_F_PER_TBL;
    float* sqy  = spy + COEF_F_PER_TBL;
    float* tile = sqy + COEF_F_PER_TBL;

    int c    = blockIdx.x % CCH;
    int g    = blockIdx.x / CCH;
    int warp = threadIdx.x >> 5;              // 16 warps; warp owns lines 2w,2w+1
    int lane = threadIdx.x & 31;              // lane = batch
    int tid  = threadIdx.x;

    // Stage this channel's packed tables (4 arrays x 16KB) with float4 copies.
    {
        const float4* src[4] = {(const float4*)g_px, (const float4*)g_qx,
                                (const float4*)g_py, (const float4*)g_qy};
        float4* dst[4] = {(float4*)spx, (float4*)sqx, (float4*)spy, (float4*)sqy};
        #pragma unroll
        for (int k = tid; k < 4096; k += NTHREADS) {
            int a  = k >> 10;                  // which table
            int j  = k & 1023;                 // f4 index within table
            int t  = j >> 8;                   // 256 f4 per (step, channel)
            int jj = j & 255;
            dst[a][t * 256 + jj] = src[a][(t * CCH + c) * 256 + jj];
        }
    }

    unsigned bpx = (unsigned)__cvta_generic_to_shared(spx);
    unsigned bqx = (unsigned)__cvta_generic_to_shared(sqx);
    unsigned bpy = (unsigned)__cvta_generic_to_shared(spy);
    unsigned bqy = (unsigned)__cvta_generic_to_shared(sqy);

    const int CHW = CCH * S * S;              // 3072
    size_t base = ((size_t)g * S) * CHW + (size_t)c * (S * S);

    // Input staging: coalesced LDG (consecutive elem per fixed batch),
    // conflict-free STS (stride 33 across lanes).
    for (int k = tid; k < S * S * S; k += NTHREADS) {
        int b = k >> 10;                      // batch within group
        int rem = k & 1023;                   // h*32+w
        tile[rem * 33 + b] = __ldg(U + base + (size_t)b * CHW + rem);
    }

    float scal = coupling[c * CCH + c];       // einsum 'cc,bchw->bchw' = diag scale
    __syncthreads();

    float rA[S], rB[S];
    int lineA = 2 * warp;
    #pragma unroll 1
    for (int t = 0; t < NSTEPS; t++) {
        unsigned off = (unsigned)((t * S + lineA) * S) * 4u;   // 128B per line table
        unsigned pax = bpx + off, qax = bqx + off;
        unsigned pay = bpy + off, qay = bqy + off;

        // x half-step #1: rows 2w,2w+1. Register input for t>0 (fused with
        // previous x2 output, same warp/lane -> no barrier in between).
        if (t == 0) solve_pair<false, true,  true>(tile, rA, rB, pax, qax, lineA, lane, 1.0f);
        else        solve_pair<false, false, true>(tile, rA, rB, pax, qax, lineA, lane, 1.0f);
        __syncthreads();

        // y full step: columns 2w,2w+1 (rA/rB reused as scratch).
        solve_pair<true, true, true>(tile, rA, rB, pay, qay, lineA, lane, 1.0f);
        __syncthreads();

        // x half-step #2: rows, channel coupling folded into output.
        // For t<3 keep results in registers only (next x1 consumes them).
        if (t == NSTEPS - 1) solve_pair<false, true, true >(tile, rA, rB, pax, qax, lineA, lane, scal);
        else                 solve_pair<false, true, false>(tile, rA, rB, pax, qax, lineA, lane, scal);
        if (t == NSTEPS - 1) __syncthreads();
    }

    // Output: conflict-free LDS, coalesced STG.
    for (int k = tid; k < S * S * S; k += NTHREADS) {
        int b = k >> 10;
        int rem = k & 1023;
        Out[base + (size_t)b * CHW + rem] = tile[rem * 33 + b];
    }
}

extern "C" void kernel_launch(void* const* d_in, const int* in_sizes, int n_in,
                              void* d_out, int out_size) {
    (void)n_in; (void)out_size;
    const float* u   = (const float*)d_in[0];
    const float* ab  = (const float*)d_in[1];
    const float* bb  = (const float*)d_in[2];
    const float* atc = (const float*)d_in[3];
    const float* btc = (const float*)d_in[4];
    const float* cc  = (const float*)d_in[5];
    int B = in_sizes[0] / (CCH * S * S);      // 16384

    cudaFuncSetAttribute(adi_kernel, cudaFuncAttributeMaxDynamicSharedMemorySize,
                         SMEM_BYTES);

    precompute_kernel<<<3, 256>>>(ab, bb, atc, btc);   // 768 lines, trivial
    adi_kernel<<<(B / S) * CCH, NTHREADS, SMEM_BYTES>>>(u, cc, (float*)d_out);
}

// round 12
// speedup vs baseline: 1.2703x; 1.2703x over previous
#include <cuda_runtime.h>

#define S 32
#define CCH 3
#define NSTEPS 4
#define DT_C 0.15f
#define EPS_C 1e-6f
#define NTHREADS 512
#define BPC 16              // batches per CTA

// Coefficient tables in pair-interleaved layout, per (t, c):
//   [type p=0 / q=1][pair 0..15][j 0..7][half 0..1][elem 0..3]
// = 2048 floats per (t,c) per direction. A half-warp's v4 load hits a 16B
// sub-block; the two halves' blocks are 16B apart -> disjoint banks, aligned.
__device__ float4 g_cx4[NSTEPS * CCH * 512];
__device__ float4 g_cy4[NSTEPS * CCH * 512];

__global__ void precompute_kernel(const float* __restrict__ alpha_base,
                                  const float* __restrict__ beta_base,
                                  const float* __restrict__ alpha_tc,
                                  const float* __restrict__ beta_tc) {
    int idx = blockIdx.x * blockDim.x + threadIdx.x;
    const int NLINES = NSTEPS * CCH * S;      // 384 per direction
    if (idx >= 2 * NLINES) return;
    int dir  = idx / NLINES;                  // 0 = x (solve along W), 1 = y (along H)
    int r    = idx % NLINES;
    int t    = r / (CCH * S);
    int c    = (r / S) % CCH;
    int line = r % S;                          // h for x-dir, w for y-dir

    float tv = (float)t * DT_C;
    const float* base = dir ? beta_base : alpha_base;
    const float* tc   = dir ? beta_tc   : alpha_tc;

    float raw[S];
    #pragma unroll
    for (int i = 0; i < S; i++) {
        int h = dir ? i : line;
        int w = dir ? line : i;
        int off = (c * S + h) * S + w;
        raw[i] = fmaxf(base[off] + tc[off] * tv, EPS_C);
    }
    float dt = dir ? DT_C : (DT_C * 0.5f);
    float cf[S];
    #pragma unroll
    for (int i = 0; i < S; i++) {
        float lm = raw[i == 0 ? 0 : i - 1];
        float rm = raw[i == S - 1 ? S - 1 : i + 1];
        cf[i] = (lm + raw[i] + rm) * (1.0f / 3.0f) * dt;
    }
    // Pairing: x pairs adjacent rows (h, h+1); y pairs columns (w, w+16).
    int pair, half;
    if (dir == 0) { pair = line >> 1;  half = line & 1;  }
    else          { pair = line & 15;  half = line >> 4; }
    float* out = dir ? (float*)g_cy4 : (float*)g_cx4;
    long tb = (long)(t * CCH + c) * 2048;      // p block; q block at +1024

    float cp = 0.0f;
    #pragma unroll
    for (int i = 0; i < S; i++) {
        float b = 1.0f + 2.0f * cf[i];
        if (i == 0 || i == S - 1) b = 1.0f + cf[i];
        float a = -cf[i];
        float denom = b - a * cp + EPS_C;     // matches reference (+EPS every step)
        float p = 1.0f / denom;
        float q = a * p;                      // also equals cstar_i (a == c)
        cp = q;
        long pos = pair * 64 + (i >> 2) * 8 + half * 4 + (i & 3);
        out[tb + pos]        = p;
        out[tb + 1024 + pos] = q;
    }
}

// One tridiagonal sweep; each lane owns (line = its half-warp's line,
// batch = lane&15), serial dim in registers. STRIDE: tile word-stride per
// position (17 for rows, 560 for columns). Coeff v4 broadcasts are asm-pinned
// (no hoist -> no spills; proven since R3). cp/cq = byte addrs for this lane's
// half-warp coeff block (p / q).
template<int STRIDE, bool IN_SMEM, bool OUT_SMEM>
__device__ __forceinline__ void solve16(float* __restrict__ tile, float (&r)[S],
                                        int dbase, unsigned cp, unsigned cq,
                                        float scale) {
    float prev = 0.0f;
    #pragma unroll
    for (int j = 0; j < 8; j++) {
        float p0, p1, p2, p3, q0, q1, q2, q3;
        asm volatile("ld.shared.v4.f32 {%0,%1,%2,%3},[%4];"
                     : "=f"(p0), "=f"(p1), "=f"(p2), "=f"(p3) : "r"(cp + 32u * j));
        asm volatile("ld.shared.v4.f32 {%0,%1,%2,%3},[%4];"
                     : "=f"(q0), "=f"(q1), "=f"(q2), "=f"(q3) : "r"(cq + 32u * j));
        #pragma unroll
        for (int e = 0; e < 4; e++) {
            int i = 4 * j + e;
            float p = e == 0 ? p0 : e == 1 ? p1 : e == 2 ? p2 : p3;
            float q = e == 0 ? q0 : e == 1 ? q1 : e == 2 ? q2 : q3;
            float d = IN_SMEM ? tile[dbase + i * STRIDE] : r[i];
            prev = fmaf(-q, prev, d * p);     // (d - a*prev)/denom
            r[i] = prev;
        }
    }
    float x = r[S - 1];                        // cstar[N-1] irrelevant (x_N = 0)
    r[S - 1] = x * scale;
    if (OUT_SMEM) tile[dbase + (S - 1) * STRIDE] = x * scale;
    #pragma unroll
    for (int j = 7; j >= 0; j--) {
        float q0, q1, q2, q3;                  // q-only reload
        asm volatile("ld.shared.v4.f32 {%0,%1,%2,%3},[%4];"
                     : "=f"(q0), "=f"(q1), "=f"(q2), "=f"(q3) : "r"(cq + 32u * j));
        #pragma unroll
        for (int e = 3; e >= 0; e--) {
            int i = 4 * j + e;
            if (i == S - 1) continue;          // seed already placed
            float q = e == 0 ? q0 : e == 1 ? q1 : e == 2 ? q2 : q3;
            x = fmaf(-q, x, r[i]);             // cstar_i == q_i
            r[i] = x * scale;
            if (OUT_SMEM) tile[dbase + i * STRIDE] = x * scale;
        }
    }
}

// Smem word map: xbuf0 @0, xbuf1 @2048, ybuf @4096, tile @6144 (17903 words).
#define W_XBUF0 0
#define W_XBUF1 2048
#define W_YBUF  4096
#define W_TILE  6144
#define TILE_WORDS (1023 * 17 + 31 * 16 + 15 + 1)            // 17903
#define SMEM_BYTES ((W_TILE + TILE_WORDS) * 4)               // 96188 B

__global__ void __launch_bounds__(NTHREADS, 2)
adi_kernel(const float* __restrict__ U, const float* __restrict__ coupling,
           float* __restrict__ Out) {
    extern __shared__ float smem[];
    float* tile = smem + W_TILE;

    int c    = blockIdx.x % CCH;
    int g    = blockIdx.x / CCH;
    int warp = threadIdx.x >> 5;              // 16 warps = 16 line-pairs
    int lane = threadIdx.x & 31;
    int bl   = lane & 15;                     // batch within CTA
    int ls   = lane >> 4;                     // half-warp line select
    int tid  = threadIdx.x;

    unsigned sb = (unsigned)__cvta_generic_to_shared(smem);

    // Stage step-0 tables (x -> xbuf0, y -> ybuf). 512 f4 each, 1 per thread.
    {
        long cb = (long)(0 * CCH + c) * 512;
        ((float4*)(smem + W_XBUF0))[tid] = g_cx4[cb + tid];
        ((float4*)(smem + W_YBUF ))[tid] = g_cy4[cb + tid];
    }

    const int CHW = CCH * S * S;              // 3072
    size_t base = ((size_t)g * BPC) * CHW + (size_t)c * (S * S);

    // Input: coalesced LDG, conflict-free STS (addr = e*17 + (e>>5)*16 + b).
    for (int k = tid; k < BPC * 1024; k += NTHREADS) {
        int b = k >> 10;
        int e = k & 1023;
        tile[e * 17 + (e >> 5) * 16 + b] = __ldg(U + base + (size_t)b * CHW + e);
    }

    float scal = coupling[c * CCH + c];       // per-channel diagonal scale
    __syncthreads();

    // Per-lane tile bases: x rows (line = 2*warp + ls), y cols (warp + 16*ls).
    int dbx = (2 * warp + ls) * 560 + bl;     // addr(e)=e*17+(e>>5)*16+b, e=line*32+i
    int dby = (warp + 16 * ls) * 17 + bl;     // e = i*32+line -> base + i*560
    unsigned clane = (unsigned)(warp * 256 + ls * 16);

    float r[S];
    #pragma unroll 1
    for (int t = 0; t < NSTEPS; t++) {
        unsigned xb = sb + (unsigned)((t & 1) ? W_XBUF1 : W_XBUF0) * 4u;
        unsigned yb = sb + (unsigned)W_YBUF * 4u;
        unsigned cpx = xb + clane, cqx = xb + 4096u + clane;
        unsigned cpy = yb + clane, cqy = yb + 4096u + clane;

        // x half-step #1 (rows): register input for t>0 (fused with prior x2).
        if (t == 0) solve16<17, true,  true>(tile, r, dbx, cpx, cqx, 1.0f);
        else        solve16<17, false, true>(tile, r, dbx, cpx, cqx, 1.0f);
        __syncthreads();                                   // bar A

        // Stage x(t+1) into the other ping-pong buffer (no readers yet).
        if (t < NSTEPS - 1) {
            unsigned nxt = (t & 1) ? W_XBUF0 : W_XBUF1;
            ((float4*)(smem + nxt))[tid] = g_cx4[(long)((t + 1) * CCH + c) * 512 + tid];
        }

        // y full step (columns); r reused as scratch.
        solve16<560, true, true>(tile, r, dby, cpy, cqy, 1.0f);
        __syncthreads();                                   // bar B

        // Stage y(t+1) (readers of y(t) are done; next read after bar A(t+1)).
        if (t < NSTEPS - 1)
            ((float4*)(smem + W_YBUF))[tid] = g_cy4[(long)((t + 1) * CCH + c) * 512 + tid];

        // x half-step #2: coupling folded into output; regs-only for t<3.
        if (t == NSTEPS - 1) solve16<17, true, true >(tile, r, dbx, cpx, cqx, scal);
        else                 solve16<17, true, false>(tile, r, dbx, cpx, cqx, scal);
        if (t == NSTEPS - 1) __syncthreads();
    }

    // Output: conflict-free LDS, coalesced STG.
    for (int k = tid; k < BPC * 1024; k += NTHREADS) {
        int b = k >> 10;
        int e = k & 1023;
        Out[base + (size_t)b * CHW + e] = tile[e * 17 + (e >> 5) * 16 + b];
    }
}

extern "C" void kernel_launch(void* const* d_in, const int* in_sizes, int n_in,
                              void* d_out, int out_size) {
    (void)n_in; (void)out_size;
    const float* u   = (const float*)d_in[0];
    const float* ab  = (const float*)d_in[1];
    const float* bb  = (const float*)d_in[2];
    const float* atc = (const float*)d_in[3];
    const float* btc = (const float*)d_in[4];
    const float* cc  = (const float*)d_in[5];
    int B = in_sizes[0] / (CCH * S * S);      // 16384

    cudaFuncSetAttribute(adi_kernel, cudaFuncAttributeMaxDynamicSharedMemorySize,
                         SMEM_BYTES);

    precompute_kernel<<<3, 256>>>(ab, bb, atc, btc);   // 768 lines, trivial
    adi_kernel<<<(B / BPC) * CCH, NTHREADS, SMEM_BYTES>>>(u, cc, (float*)d_out);
}

// round 13
// speedup vs baseline: 1.2711x; 1.0006x over previous
#include <cuda_runtime.h>

#define S 32
#define CCH 3
#define NSTEPS 4
#define DT_C 0.15f
#define EPS_C 1e-6f
#define NTHREADS 512
#define BPC 16              // batches per CTA

// Coefficient tables in pair-interleaved layout, per (t, c):
//   [type p=0 / q=1][pair 0..15][j 0..7][half 0..1][elem 0..3]
// = 2048 floats per (t,c) per direction. A half-warp's v4 load hits a 16B
// sub-block; the two halves' blocks are 16B apart -> disjoint banks, aligned.
__device__ float4 g_cx4[NSTEPS * CCH * 512];
__device__ float4 g_cy4[NSTEPS * CCH * 512];

__global__ void precompute_kernel(const float* __restrict__ alpha_base,
                                  const float* __restrict__ beta_base,
                                  const float* __restrict__ alpha_tc,
                                  const float* __restrict__ beta_tc) {
    int idx = blockIdx.x * blockDim.x + threadIdx.x;
    const int NLINES = NSTEPS * CCH * S;      // 384 per direction
    if (idx >= 2 * NLINES) return;
    int dir  = idx / NLINES;                  // 0 = x (solve along W), 1 = y (along H)
    int r    = idx % NLINES;
    int t    = r / (CCH * S);
    int c    = (r / S) % CCH;
    int line = r % S;                          // h for x-dir, w for y-dir

    float tv = (float)t * DT_C;
    const float* base = dir ? beta_base : alpha_base;
    const float* tc   = dir ? beta_tc   : alpha_tc;

    float raw[S];
    #pragma unroll
    for (int i = 0; i < S; i++) {
        int h = dir ? i : line;
        int w = dir ? line : i;
        int off = (c * S + h) * S + w;
        raw[i] = fmaxf(base[off] + tc[off] * tv, EPS_C);
    }
    float dt = dir ? DT_C : (DT_C * 0.5f);
    float cf[S];
    #pragma unroll
    for (int i = 0; i < S; i++) {
        float lm = raw[i == 0 ? 0 : i - 1];
        float rm = raw[i == S - 1 ? S - 1 : i + 1];
        cf[i] = (lm + raw[i] + rm) * (1.0f / 3.0f) * dt;
    }
    // Pairing: x pairs adjacent rows (h, h+1); y pairs columns (w, w+16).
    int pair, half;
    if (dir == 0) { pair = line >> 1;  half = line & 1;  }
    else          { pair = line & 15;  half = line >> 4; }
    float* out = dir ? (float*)g_cy4 : (float*)g_cx4;
    long tb = (long)(t * CCH + c) * 2048;      // p block; q block at +1024

    float cp = 0.0f;
    #pragma unroll
    for (int i = 0; i < S; i++) {
        float b = 1.0f + 2.0f * cf[i];
        if (i == 0 || i == S - 1) b = 1.0f + cf[i];
        float a = -cf[i];
        float denom = b - a * cp + EPS_C;     // matches reference (+EPS every step)
        float p = 1.0f / denom;
        float q = a * p;                      // also equals cstar_i (a == c)
        cp = q;
        long pos = pair * 64 + (i >> 2) * 8 + half * 4 + (i & 3);
        out[tb + pos]        = p;
        out[tb + 1024 + pos] = q;
    }
}

// One tridiagonal sweep; each lane owns (line = its half-warp's line,
// batch = lane&15), serial dim in registers. STRIDE: tile word-stride per
// position (17 for rows, 560 for columns). Coeff v4 broadcasts are asm-pinned
// (no hoist -> no spills; proven since R3). cp/cq = byte addrs for this lane's
// half-warp coeff block (p / q).
template<int STRIDE, bool IN_SMEM, bool OUT_SMEM>
__device__ __forceinline__ void solve16(float* __restrict__ tile, float (&r)[S],
                                        int dbase, unsigned cp, unsigned cq,
                                        float scale) {
    float prev = 0.0f;
    #pragma unroll
    for (int j = 0; j < 8; j++) {
        float p0, p1, p2, p3, q0, q1, q2, q3;
        asm volatile("ld.shared.v4.f32 {%0,%1,%2,%3},[%4];"
                     : "=f"(p0), "=f"(p1), "=f"(p2), "=f"(p3) : "r"(cp + 32u * j));
        asm volatile("ld.shared.v4.f32 {%0,%1,%2,%3},[%4];"
                     : "=f"(q0), "=f"(q1), "=f"(q2), "=f"(q3) : "r"(cq + 32u * j));
        #pragma unroll
        for (int e = 0; e < 4; e++) {
            int i = 4 * j + e;
            float p = e == 0 ? p0 : e == 1 ? p1 : e == 2 ? p2 : p3;
            float q = e == 0 ? q0 : e == 1 ? q1 : e == 2 ? q2 : q3;
            float d = IN_SMEM ? tile[dbase + i * STRIDE] : r[i];
            prev = fmaf(-q, prev, d * p);     // (d - a*prev)/denom
            r[i] = prev;
        }
    }
    float x = r[S - 1];                        // cstar[N-1] irrelevant (x_N = 0)
    r[S - 1] = x * scale;
    if (OUT_SMEM) tile[dbase + (S - 1) * STRIDE] = x * scale;
    #pragma unroll
    for (int j = 7; j >= 0; j--) {
        float q0, q1, q2, q3;                  // q-only reload
        asm volatile("ld.shared.v4.f32 {%0,%1,%2,%3},[%4];"
                     : "=f"(q0), "=f"(q1), "=f"(q2), "=f"(q3) : "r"(cq + 32u * j));
        #pragma unroll
        for (int e = 3; e >= 0; e--) {
            int i = 4 * j + e;
            if (i == S - 1) continue;          // seed already placed
            float q = e == 0 ? q0 : e == 1 ? q1 : e == 2 ? q2 : q3;
            x = fmaf(-q, x, r[i]);             // cstar_i == q_i
            r[i] = x * scale;
            if (OUT_SMEM) tile[dbase + i * STRIDE] = x * scale;
        }
    }
}

// Smem word map: xbuf0 @0, xbuf1 @2048, ybuf @4096, tile @6144 (17903 words).
#define W_XBUF0 0
#define W_XBUF1 2048
#define W_YBUF  4096
#define W_TILE  6144
#define TILE_WORDS (1023 * 17 + 31 * 16 + 15 + 1)            // 17903
#define SMEM_BYTES ((W_TILE + TILE_WORDS) * 4)               // 96188 B

__global__ void __launch_bounds__(NTHREADS, 2)
adi_kernel(const float* __restrict__ U, const float* __restrict__ coupling,
           float* __restrict__ Out) {
    extern __shared__ float smem[];
    float* tile = smem + W_TILE;

    int c    = blockIdx.x % CCH;
    int g    = blockIdx.x / CCH;
    int warp = threadIdx.x >> 5;              // 16 warps = 16 line-pairs
    int lane = threadIdx.x & 31;
    int bl   = lane & 15;                     // batch within CTA
    int ls   = lane >> 4;                     // half-warp line select
    int tid  = threadIdx.x;

    unsigned sb = (unsigned)__cvta_generic_to_shared(smem);

    // Stage step-0 tables (x -> xbuf0, y -> ybuf). 512 f4 each, 1 per thread.
    {
        long cb = (long)(0 * CCH + c) * 512;
        ((float4*)(smem + W_XBUF0))[tid] = g_cx4[cb + tid];
        ((float4*)(smem + W_YBUF ))[tid] = g_cy4[cb + tid];
    }

    const int CHW = CCH * S * S;              // 3072
    size_t base = ((size_t)g * BPC) * CHW + (size_t)c * (S * S);

    // Input: coalesced LDG, conflict-free STS (addr = e*17 + (e>>5)*16 + b).
    for (int k = tid; k < BPC * 1024; k += NTHREADS) {
        int b = k >> 10;
        int e = k & 1023;
        tile[e * 17 + (e >> 5) * 16 + b] = __ldg(U + base + (size_t)b * CHW + e);
    }

    float scal = coupling[c * CCH + c];       // per-channel diagonal scale
    __syncthreads();

    // Per-lane tile bases: x rows (line = 2*warp + ls), y cols (warp + 16*ls).
    int dbx = (2 * warp + ls) * 560 + bl;     // addr(e)=e*17+(e>>5)*16+b, e=line*32+i
    int dby = (warp + 16 * ls) * 17 + bl;     // e = i*32+line -> base + i*560
    unsigned clane = (unsigned)(warp * 256 + ls * 16);

    float r[S];
    #pragma unroll 1
    for (int t = 0; t < NSTEPS; t++) {
        unsigned xb = sb + (unsigned)((t & 1) ? W_XBUF1 : W_XBUF0) * 4u;
        unsigned yb = sb + (unsigned)W_YBUF * 4u;
        unsigned cpx = xb + clane, cqx = xb + 4096u + clane;
        unsigned cpy = yb + clane, cqy = yb + 4096u + clane;

        // x half-step #1 (rows): register input for t>0 (fused with prior x2).
        if (t == 0) solve16<17, true,  true>(tile, r, dbx, cpx, cqx, 1.0f);
        else        solve16<17, false, true>(tile, r, dbx, cpx, cqx, 1.0f);
        __syncthreads();                                   // bar A

        // Stage x(t+1) into the other ping-pong buffer (no readers yet).
        if (t < NSTEPS - 1) {
            unsigned nxt = (t & 1) ? W_XBUF0 : W_XBUF1;
            ((float4*)(smem + nxt))[tid] = g_cx4[(long)((t + 1) * CCH + c) * 512 + tid];
        }

        // y full step (columns); r reused as scratch.
        solve16<560, true, true>(tile, r, dby, cpy, cqy, 1.0f);
        __syncthreads();                                   // bar B

        // Stage y(t+1) (readers of y(t) are done; next read after bar A(t+1)).
        if (t < NSTEPS - 1)
            ((float4*)(smem + W_YBUF))[tid] = g_cy4[(long)((t + 1) * CCH + c) * 512 + tid];

        // x half-step #2: coupling folded into output; regs-only for t<3.
        if (t == NSTEPS - 1) solve16<17, true, true >(tile, r, dbx, cpx, cqx, scal);
        else                 solve16<17, true, false>(tile, r, dbx, cpx, cqx, scal);
        if (t == NSTEPS - 1) __syncthreads();
    }

    // Output: conflict-free LDS, coalesced STG.
    for (int k = tid; k < BPC * 1024; k += NTHREADS) {
        int b = k >> 10;
        int e = k & 1023;
        Out[base + (size_t)b * CHW + e] = tile[e * 17 + (e >> 5) * 16 + b];
    }
}

extern "C" void kernel_launch(void* const* d_in, const int* in_sizes, int n_in,
                              void* d_out, int out_size) {
    (void)n_in; (void)out_size;
    const float* u   = (const float*)d_in[0];
    const float* ab  = (const float*)d_in[1];
    const float* bb  = (const float*)d_in[2];
    const float* atc = (const float*)d_in[3];
    const float* btc = (const float*)d_in[4];
    const float* cc  = (const float*)d_in[5];
    int B = in_sizes[0] / (CCH * S * S);      // 16384

    cudaFuncSetAttribute(adi_kernel, cudaFuncAttributeMaxDynamicSharedMemorySize,
                         SMEM_BYTES);

    precompute_kernel<<<3, 256>>>(ab, bb, atc, btc);   // 768 lines, trivial
    adi_kernel<<<(B / BPC) * CCH, NTHREADS, SMEM_BYTES>>>(u, cc, (float*)d_out);
}

// round 14
// speedup vs baseline: 1.2730x; 1.0015x over previous
#include <cuda_runtime.h>

#define S 32
#define CCH 3
#define NSTEPS 4
#define DT_C 0.15f
#define EPS_C 1e-6f
#define NTHREADS 512
#define BPC 16              // batches per CTA

// Coefficient tables in pair-interleaved layout, per (t, c):
//   [type p=0 / q=1][pair 0..15][j 0..7][half 0..1][elem 0..3]
// = 2048 floats per (t,c) per direction. A half-warp's v4 load hits a 16B
// sub-block; the two halves' blocks are 16B apart -> disjoint banks, aligned.
__device__ float4 g_cx4[NSTEPS * CCH * 512];
__device__ float4 g_cy4[NSTEPS * CCH * 512];

__global__ void precompute_kernel(const float* __restrict__ alpha_base,
                                  const float* __restrict__ beta_base,
                                  const float* __restrict__ alpha_tc,
                                  const float* __restrict__ beta_tc) {
    int idx = blockIdx.x * blockDim.x + threadIdx.x;
    const int NLINES = NSTEPS * CCH * S;      // 384 per direction
    if (idx >= 2 * NLINES) return;
    int dir  = idx / NLINES;                  // 0 = x (solve along W), 1 = y (along H)
    int r    = idx % NLINES;
    int t    = r / (CCH * S);
    int c    = (r / S) % CCH;
    int line = r % S;                          // h for x-dir, w for y-dir

    float tv = (float)t * DT_C;
    const float* base = dir ? beta_base : alpha_base;
    const float* tc   = dir ? beta_tc   : alpha_tc;

    float raw[S];
    #pragma unroll
    for (int i = 0; i < S; i++) {
        int h = dir ? i : line;
        int w = dir ? line : i;
        int off = (c * S + h) * S + w;
        raw[i] = fmaxf(base[off] + tc[off] * tv, EPS_C);
    }
    float dt = dir ? DT_C : (DT_C * 0.5f);
    float cf[S];
    #pragma unroll
    for (int i = 0; i < S; i++) {
        float lm = raw[i == 0 ? 0 : i - 1];
        float rm = raw[i == S - 1 ? S - 1 : i + 1];
        cf[i] = (lm + raw[i] + rm) * (1.0f / 3.0f) * dt;
    }
    // Pairing: x pairs adjacent rows (h, h+1); y pairs columns (w, w+16).
    int pair, half;
    if (dir == 0) { pair = line >> 1;  half = line & 1;  }
    else          { pair = line & 15;  half = line >> 4; }
    float* out = dir ? (float*)g_cy4 : (float*)g_cx4;
    long tb = (long)(t * CCH + c) * 2048;      // p block; q block at +1024

    float cp = 0.0f;
    #pragma unroll
    for (int i = 0; i < S; i++) {
        float b = 1.0f + 2.0f * cf[i];
        if (i == 0 || i == S - 1) b = 1.0f + cf[i];
        float a = -cf[i];
        float denom = b - a * cp + EPS_C;     // matches reference (+EPS every step)
        float p = 1.0f / denom;
        float q = a * p;                      // also equals cstar_i (a == c)
        cp = q;
        long pos = pair * 64 + (i >> 2) * 8 + half * 4 + (i & 3);
        out[tb + pos]        = p;
        out[tb + 1024 + pos] = q;
    }
}

// One tridiagonal sweep; each lane owns (line = its half-warp's line,
// batch = lane&15), serial dim in registers. STRIDE: tile word-stride per
// position (17 for rows, 560 for columns). Coeff v4 broadcasts are asm-pinned
// (no hoist -> no spills; proven since R3). cp/cq = byte addrs for this lane's
// half-warp coeff block (p / q).
template<int STRIDE, bool IN_SMEM, bool OUT_SMEM>
__device__ __forceinline__ void solve16(float* __restrict__ tile, float (&r)[S],
                                        int dbase, unsigned cp, unsigned cq,
                                        float scale) {
    float prev = 0.0f;
    #pragma unroll
    for (int j = 0; j < 8; j++) {
        float p0, p1, p2, p3, q0, q1, q2, q3;
        asm volatile("ld.shared.v4.f32 {%0,%1,%2,%3},[%4];"
                     : "=f"(p0), "=f"(p1), "=f"(p2), "=f"(p3) : "r"(cp + 32u * j));
        asm volatile("ld.shared.v4.f32 {%0,%1,%2,%3},[%4];"
                     : "=f"(q0), "=f"(q1), "=f"(q2), "=f"(q3) : "r"(cq + 32u * j));
        #pragma unroll
        for (int e = 0; e < 4; e++) {
            int i = 4 * j + e;
            float p = e == 0 ? p0 : e == 1 ? p1 : e == 2 ? p2 : p3;
            float q = e == 0 ? q0 : e == 1 ? q1 : e == 2 ? q2 : q3;
            float d = IN_SMEM ? tile[dbase + i * STRIDE] : r[i];
            prev = fmaf(-q, prev, d * p);     // (d - a*prev)/denom
            r[i] = prev;
        }
    }
    float x = r[S - 1];                        // cstar[N-1] irrelevant (x_N = 0)
    r[S - 1] = x * scale;
    if (OUT_SMEM) tile[dbase + (S - 1) * STRIDE] = x * scale;
    #pragma unroll
    for (int j = 7; j >= 0; j--) {
        float q0, q1, q2, q3;                  // q-only reload
        asm volatile("ld.shared.v4.f32 {%0,%1,%2,%3},[%4];"
                     : "=f"(q0), "=f"(q1), "=f"(q2), "=f"(q3) : "r"(cq + 32u * j));
        #pragma unroll
        for (int e = 3; e >= 0; e--) {
            int i = 4 * j + e;
            if (i == S - 1) continue;          // seed already placed
            float q = e == 0 ? q0 : e == 1 ? q1 : e == 2 ? q2 : q3;
            x = fmaf(-q, x, r[i]);             // cstar_i == q_i
            r[i] = x * scale;
            if (OUT_SMEM) tile[dbase + i * STRIDE] = x * scale;
        }
    }
}

// Smem word map: xbuf0 @0, xbuf1 @2048, ybuf @4096, tile @6144 (17903 words).
#define W_XBUF0 0
#define W_XBUF1 2048
#define W_YBUF  4096
#define W_TILE  6144
#define TILE_WORDS (1023 * 17 + 31 * 16 + 15 + 1)            // 17903
#define SMEM_BYTES ((W_TILE + TILE_WORDS) * 4)               // 96188 B

__global__ void __launch_bounds__(NTHREADS, 2)
adi_kernel(const float* __restrict__ U, const float* __restrict__ coupling,
           float* __restrict__ Out) {
    extern __shared__ float smem[];
    float* tile = smem + W_TILE;

    int c    = blockIdx.x % CCH;
    int g    = blockIdx.x / CCH;
    int warp = threadIdx.x >> 5;              // 16 warps = 16 line-pairs
    int lane = threadIdx.x & 31;
    int bl   = lane & 15;                     // batch within CTA
    int ls   = lane >> 4;                     // half-warp line select
    int tid  = threadIdx.x;

    unsigned sb = (unsigned)__cvta_generic_to_shared(smem);

    // Stage step-0 tables (x -> xbuf0, y -> ybuf). 512 f4 each, 1 per thread.
    {
        long cb = (long)(0 * CCH + c) * 512;
        ((float4*)(smem + W_XBUF0))[tid] = g_cx4[cb + tid];
        ((float4*)(smem + W_YBUF ))[tid] = g_cy4[cb + tid];
    }

    const int CHW = CCH * S * S;              // 3072
    size_t base = ((size_t)g * BPC) * CHW + (size_t)c * (S * S);

    // Input: coalesced LDG, conflict-free STS (addr = e*17 + (e>>5)*16 + b).
    for (int k = tid; k < BPC * 1024; k += NTHREADS) {
        int b = k >> 10;
        int e = k & 1023;
        tile[e * 17 + (e >> 5) * 16 + b] = __ldg(U + base + (size_t)b * CHW + e);
    }

    float scal = coupling[c * CCH + c];       // per-channel diagonal scale
    __syncthreads();

    // Per-lane tile bases: x rows (line = 2*warp + ls), y cols (warp + 16*ls).
    int dbx = (2 * warp + ls) * 560 + bl;     // addr(e)=e*17+(e>>5)*16+b, e=line*32+i
    int dby = (warp + 16 * ls) * 17 + bl;     // e = i*32+line -> base + i*560
    unsigned clane = (unsigned)(warp * 256 + ls * 16);

    float r[S];
    #pragma unroll 1
    for (int t = 0; t < NSTEPS; t++) {
        unsigned xb = sb + (unsigned)((t & 1) ? W_XBUF1 : W_XBUF0) * 4u;
        unsigned yb = sb + (unsigned)W_YBUF * 4u;
        unsigned cpx = xb + clane, cqx = xb + 4096u + clane;
        unsigned cpy = yb + clane, cqy = yb + 4096u + clane;

        // x half-step #1 (rows): register input for t>0 (fused with prior x2).
        if (t == 0) solve16<17, true,  true>(tile, r, dbx, cpx, cqx, 1.0f);
        else        solve16<17, false, true>(tile, r, dbx, cpx, cqx, 1.0f);
        __syncthreads();                                   // bar A

        // Stage x(t+1) into the other ping-pong buffer (no readers yet).
        if (t < NSTEPS - 1) {
            unsigned nxt = (t & 1) ? W_XBUF0 : W_XBUF1;
            ((float4*)(smem + nxt))[tid] = g_cx4[(long)((t + 1) * CCH + c) * 512 + tid];
        }

        // y full step (columns); r reused as scratch.
        solve16<560, true, true>(tile, r, dby, cpy, cqy, 1.0f);
        __syncthreads();                                   // bar B

        // Stage y(t+1) (readers of y(t) are done; next read after bar A(t+1)).
        if (t < NSTEPS - 1)
            ((float4*)(smem + W_YBUF))[tid] = g_cy4[(long)((t + 1) * CCH + c) * 512 + tid];

        // x half-step #2: coupling folded into output; regs-only for t<3.
        if (t == NSTEPS - 1) solve16<17, true, true >(tile, r, dbx, cpx, cqx, scal);
        else                 solve16<17, true, false>(tile, r, dbx, cpx, cqx, scal);
        if (t == NSTEPS - 1) __syncthreads();
    }

    // Output: conflict-free LDS, coalesced STG.
    for (int k = tid; k < BPC * 1024; k += NTHREADS) {
        int b = k >> 10;
        int e = k & 1023;
        Out[base + (size_t)b * CHW + e] = tile[e * 17 + (e >> 5) * 16 + b];
    }
}

extern "C" void kernel_launch(void* const* d_in, const int* in_sizes, int n_in,
                              void* d_out, int out_size) {
    (void)n_in; (void)out_size;
    const float* u   = (const float*)d_in[0];
    const float* ab  = (const float*)d_in[1];
    const float* bb  = (const float*)d_in[2];
    const float* atc = (const float*)d_in[3];
    const float* btc = (const float*)d_in[4];
    const float* cc  = (const float*)d_in[5];
    int B = in_sizes[0] / (CCH * S * S);      // 16384

    cudaFuncSetAttribute(adi_kernel, cudaFuncAttributeMaxDynamicSharedMemorySize,
                         SMEM_BYTES);

    precompute_kernel<<<3, 256>>>(ab, bb, atc, btc);   // 768 lines, trivial
    adi_kernel<<<(B / BPC) * CCH, NTHREADS, SMEM_BYTES>>>(u, cc, (float*)d_out);
}